// round 1
// baseline (speedup 1.0000x reference)
#include <cuda_runtime.h>
#include <math.h>

// Problem constants
#define BB  4
#define SS  512
#define DD  512
#define HH  8
#define DHH 64
#define FFD 2048
#define LL  6
#define VV  32000
#define MM  (BB*SS)        // 2048 rows
#define QKVLD (3*DD)       // 1536

// ---------------- scratch (device globals; no allocation allowed) ----------
__device__ float g_x   [MM*DD];
__device__ float g_h   [MM*DD];
__device__ float g_a   [MM*DD];
__device__ float g_qkv [MM*3*DD];
__device__ float g_sc  [BB*HH*SS*SS];
__device__ float g_ao  [MM*DD];
__device__ float g_pr  [MM*DD];
__device__ float g_ff  [MM*FFD];
__device__ float g_dp  [MM];          // decoder pad mask (tokens==0)

// ---------------- embedding + positional encoding + pad mask ---------------
__global__ void embed_kernel(const int* __restrict__ tokens,
                             const float* __restrict__ emb,
                             float* __restrict__ x, float* __restrict__ depad)
{
    int row = blockIdx.x;            // 0..MM-1  (b*S + s)
    int s   = row & (SS-1);
    int tok = tokens[row];
    if (threadIdx.x == 0) depad[row] = (tok == 0) ? 1.0f : 0.0f;
    const float sq = sqrtf((float)DD);
    for (int d = threadIdx.x; d < DD; d += blockDim.x) {
        float i   = (float)((d >> 1) << 1) / (float)DD;
        float inv = powf(10000.0f, -i);
        float em  = (float)s * inv;
        float pe  = ((d & 1) == 0) ? sinf(em) : cosf(em);
        x[row*DD + d] = emb[(size_t)tok*DD + d] * sq + pe;
    }
}

// ---------------- generic tiled SGEMM:  C = A * W^T (+bias)(+relu) ---------
// A: [M,K] row-major (lda), W: [N,K] row-major (ldw), C: [M,N] (ldc)
// grid = (N/64, M/64), block = 256
template<int BIAS, int RELU>
__global__ void __launch_bounds__(256)
gemm_nt(const float* __restrict__ A, const float* __restrict__ W,
        const float* __restrict__ bias, float* __restrict__ C,
        int K, int lda, int ldw, int ldc)
{
    __shared__ float As[16][64];
    __shared__ float Ws[16][64];
    const int m0 = blockIdx.y * 64, n0 = blockIdx.x * 64;
    const int t  = threadIdx.x;
    const int lr = t >> 2, lc = (t & 3) << 2;     // loader: row 0..63, col 0..12
    const int tx = t & 15, ty = t >> 4;           // compute: 16x16 threads
    float acc[4][4] = {};
    const float* Ap = A + (size_t)(m0 + lr) * lda + lc;
    const float* Wp = W + (size_t)(n0 + lr) * ldw + lc;
    for (int k0 = 0; k0 < K; k0 += 16) {
        float4 av = *(const float4*)(Ap + k0);
        float4 wv = *(const float4*)(Wp + k0);
        As[lc+0][lr]=av.x; As[lc+1][lr]=av.y; As[lc+2][lr]=av.z; As[lc+3][lr]=av.w;
        Ws[lc+0][lr]=wv.x; Ws[lc+1][lr]=wv.y; Ws[lc+2][lr]=wv.z; Ws[lc+3][lr]=wv.w;
        __syncthreads();
        #pragma unroll
        for (int kk = 0; kk < 16; kk++) {
            float4 ra = *(const float4*)&As[kk][ty << 2];
            float4 rb = *(const float4*)&Ws[kk][tx << 2];
            float ar[4] = {ra.x, ra.y, ra.z, ra.w};
            float br[4] = {rb.x, rb.y, rb.z, rb.w};
            #pragma unroll
            for (int i = 0; i < 4; i++)
                #pragma unroll
                for (int j = 0; j < 4; j++)
                    acc[i][j] += ar[i] * br[j];
        }
        __syncthreads();
    }
    #pragma unroll
    for (int i = 0; i < 4; i++) {
        int m = m0 + (ty << 2) + i;
        #pragma unroll
        for (int j = 0; j < 4; j++) {
            int n = n0 + (tx << 2) + j;
            float v = acc[i][j];
            if (BIAS) v += bias[n];
            if (RELU) v = fmaxf(v, 0.0f);
            C[(size_t)m * ldc + n] = v;
        }
    }
}

// ---------------- attention scores:  s = Q K^T / 8 - mask*1e6 --------------
// Q rows at qkv[.., h*64], K rows at qkv[.., 512 + h*64]; mask: [B,S] floats.
// grid = (S/64, S/64, B*H)
template<int CAUSAL>
__global__ void __launch_bounds__(256)
attn_scores(const float* __restrict__ qkv, const float* __restrict__ mask,
            float* __restrict__ scores)
{
    __shared__ float Qs[16][64];
    __shared__ float Ks[16][64];
    const int z  = blockIdx.z, b = z >> 3, h = z & 7;
    const int q0 = blockIdx.y * 64, k0v = blockIdx.x * 64;
    const int t  = threadIdx.x;
    const int lr = t >> 2, lc = (t & 3) << 2;
    const int tx = t & 15, ty = t >> 4;
    const float* Q  = qkv + (size_t)(b*SS + q0 + lr) * QKVLD + h*DHH + lc;
    const float* Kv = qkv + (size_t)(b*SS + k0v + lr) * QKVLD + DD + h*DHH + lc;
    float acc[4][4] = {};
    for (int k0 = 0; k0 < DHH; k0 += 16) {
        float4 av = *(const float4*)(Q + k0);
        float4 wv = *(const float4*)(Kv + k0);
        Qs[lc+0][lr]=av.x; Qs[lc+1][lr]=av.y; Qs[lc+2][lr]=av.z; Qs[lc+3][lr]=av.w;
        Ks[lc+0][lr]=wv.x; Ks[lc+1][lr]=wv.y; Ks[lc+2][lr]=wv.z; Ks[lc+3][lr]=wv.w;
        __syncthreads();
        #pragma unroll
        for (int kk = 0; kk < 16; kk++) {
            float4 ra = *(const float4*)&Qs[kk][ty << 2];
            float4 rb = *(const float4*)&Ks[kk][tx << 2];
            float ar[4] = {ra.x, ra.y, ra.z, ra.w};
            float br[4] = {rb.x, rb.y, rb.z, rb.w};
            #pragma unroll
            for (int i = 0; i < 4; i++)
                #pragma unroll
                for (int j = 0; j < 4; j++)
                    acc[i][j] += ar[i] * br[j];
        }
        __syncthreads();
    }
    #pragma unroll
    for (int i = 0; i < 4; i++) {
        int qq = q0 + (ty << 2) + i;
        #pragma unroll
        for (int j = 0; j < 4; j++) {
            int kq = k0v + (tx << 2) + j;
            float mv = mask[b*SS + kq];
            if (CAUSAL && kq > qq) mv = 1.0f;     // max(de_pad, tri)
            scores[((size_t)z*SS + qq)*SS + kq] = acc[i][j] * 0.125f - mv * 1e6f;
        }
    }
}

// ---------------- row softmax over width 512 --------------------------------
__global__ void __launch_bounds__(256) softmax512(float* __restrict__ s)
{
    __shared__ float red[256];
    float* p = s + (size_t)blockIdx.x * SS;
    int t = threadIdx.x;
    float a = p[t], b = p[t + 256];
    red[t] = fmaxf(a, b);
    __syncthreads();
    for (int o = 128; o > 0; o >>= 1) { if (t < o) red[t] = fmaxf(red[t], red[t+o]); __syncthreads(); }
    float m = red[0];
    __syncthreads();
    float e0 = expf(a - m), e1 = expf(b - m);
    red[t] = e0 + e1;
    __syncthreads();
    for (int o = 128; o > 0; o >>= 1) { if (t < o) red[t] += red[t+o]; __syncthreads(); }
    float inv = 1.0f / red[0];
    p[t] = e0 * inv;
    p[t + 256] = e1 * inv;
}

// ---------------- attention * V :  O[b,q,h*64+d] = sum_k P[q,k] V[k,d] ------
// grid = (1, S/64, B*H)
__global__ void __launch_bounds__(256)
attn_av(const float* __restrict__ scores, const float* __restrict__ qkv,
        float* __restrict__ o)
{
    __shared__ float Ps[16][64];
    __shared__ float Vs[16][64];
    const int z  = blockIdx.z, b = z >> 3, h = z & 7;
    const int q0 = blockIdx.y * 64;
    const int t  = threadIdx.x;
    const int lr = t >> 2, lc = (t & 3) << 2;     // P loader
    const int vr = t >> 4, vc = (t & 15) << 2;    // V loader (16 x 64 direct)
    const int tx = t & 15, ty = t >> 4;
    const float* P = scores + ((size_t)z*SS + q0) * SS;
    const float* V = qkv + (size_t)(b*SS) * QKVLD + 2*DD + h*DHH;
    float acc[4][4] = {};
    for (int k0 = 0; k0 < SS; k0 += 16) {
        float4 pv = *(const float4*)(P + (size_t)lr*SS + k0 + lc);
        Ps[lc+0][lr]=pv.x; Ps[lc+1][lr]=pv.y; Ps[lc+2][lr]=pv.z; Ps[lc+3][lr]=pv.w;
        float4 vv = *(const float4*)(V + (size_t)(k0 + vr)*QKVLD + vc);
        *(float4*)&Vs[vr][vc] = vv;
        __syncthreads();
        #pragma unroll
        for (int kk = 0; kk < 16; kk++) {
            float4 ra = *(const float4*)&Ps[kk][ty << 2];
            float4 rb = *(const float4*)&Vs[kk][tx << 2];
            float ar[4] = {ra.x, ra.y, ra.z, ra.w};
            float br[4] = {rb.x, rb.y, rb.z, rb.w};
            #pragma unroll
            for (int i = 0; i < 4; i++)
                #pragma unroll
                for (int j = 0; j < 4; j++)
                    acc[i][j] += ar[i] * br[j];
        }
        __syncthreads();
    }
    #pragma unroll
    for (int i = 0; i < 4; i++)
        #pragma unroll
        for (int j = 0; j < 4; j++)
            o[(size_t)(b*SS + q0 + (ty<<2) + i) * DD + h*DHH + (tx<<2) + j] = acc[i][j];
}

// ---------------- fused residual add + LayerNorm ----------------------------
__global__ void __launch_bounds__(256)
add_ln(const float* __restrict__ x1, const float* __restrict__ x2,
       const float* __restrict__ g, const float* __restrict__ bb,
       float* __restrict__ y)
{
    __shared__ float red[256];
    const int row = blockIdx.x, t = threadIdx.x;
    const size_t base = (size_t)row * DD;
    float a = x1[base + t]       + x2[base + t];
    float c = x1[base + t + 256] + x2[base + t + 256];
    red[t] = a + c;
    __syncthreads();
    for (int o = 128; o > 0; o >>= 1) { if (t < o) red[t] += red[t+o]; __syncthreads(); }
    float mu = red[0] * (1.0f / DD);
    __syncthreads();
    float da = a - mu, dc = c - mu;
    red[t] = da*da + dc*dc;
    __syncthreads();
    for (int o = 128; o > 0; o >>= 1) { if (t < o) red[t] += red[t+o]; __syncthreads(); }
    float inv = rsqrtf(red[0] * (1.0f / DD) + 1e-6f);
    y[base + t]       = da * inv * g[t]       + bb[t];
    y[base + t + 256] = dc * inv * g[t + 256] + bb[t + 256];
}

// ---------------- launch ----------------------------------------------------
extern "C" void kernel_launch(void* const* d_in, const int* in_sizes, int n_in,
                              void* d_out, int out_size)
{
    const int*   tokens = (const int*)  d_in[0];
    const float* en_out = (const float*)d_in[1];
    const float* en_pad = (const float*)d_in[2];   // [B,1,1,S] -> [B,S]
    const float* emb    = (const float*)d_in[3];
    const float* sa_w   = (const float*)d_in[4];
    const float* sa_b   = (const float*)d_in[5];
    const float* ca_w   = (const float*)d_in[6];
    const float* ca_b   = (const float*)d_in[7];
    const float* ff_w1  = (const float*)d_in[8];
    const float* ff_b1  = (const float*)d_in[9];
    const float* ff_w2  = (const float*)d_in[10];
    const float* ff_b2  = (const float*)d_in[11];
    const float* ln_g   = (const float*)d_in[12];
    const float* ln_b   = (const float*)d_in[13];
    const float* out_w  = (const float*)d_in[14];
    const float* out_b  = (const float*)d_in[15];
    float* out = (float*)d_out;

    float *x, *h, *a, *qkv, *sc, *ao, *pr, *ff, *dp;
    cudaGetSymbolAddress((void**)&x,   g_x);
    cudaGetSymbolAddress((void**)&h,   g_h);
    cudaGetSymbolAddress((void**)&a,   g_a);
    cudaGetSymbolAddress((void**)&qkv, g_qkv);
    cudaGetSymbolAddress((void**)&sc,  g_sc);
    cudaGetSymbolAddress((void**)&ao,  g_ao);
    cudaGetSymbolAddress((void**)&pr,  g_pr);
    cudaGetSymbolAddress((void**)&ff,  g_ff);
    cudaGetSymbolAddress((void**)&dp,  g_dp);

    embed_kernel<<<MM, 256>>>(tokens, emb, x, dp);

    const dim3 gAttnS(SS/64, SS/64, BB*HH);   // scores
    const dim3 gAttnV(1,     SS/64, BB*HH);   // P @ V
    const int  nSoft = BB*HH*SS;

    for (int i = 0; i < LL; i++) {
        const float* saw = sa_w + (size_t)i*4*DD*DD;
        const float* sab = sa_b + (size_t)i*4*DD;
        const float* caw = ca_w + (size_t)i*4*DD*DD;
        const float* cab = ca_b + (size_t)i*4*DD;

        // ---- self attention ----
        gemm_nt<1,0><<<dim3(3*DD/64, MM/64), 256>>>(x,  saw,          sab,        qkv, DD, DD, DD, QKVLD);
        attn_scores<1><<<gAttnS, 256>>>(qkv, dp, sc);
        softmax512<<<nSoft, 256>>>(sc);
        attn_av<<<gAttnV, 256>>>(sc, qkv, ao);
        gemm_nt<1,0><<<dim3(DD/64, MM/64), 256>>>(ao, saw + 3*DD*DD, sab + 3*DD, pr,  DD, DD, DD, DD);
        add_ln<<<MM, 256>>>(x, pr, ln_g + (size_t)(i*3+0)*DD, ln_b + (size_t)(i*3+0)*DD, h);

        // ---- cross attention ----
        gemm_nt<1,0><<<dim3(DD/64,   MM/64), 256>>>(h,      caw,          cab,       qkv,      DD, DD, DD, QKVLD);
        gemm_nt<1,0><<<dim3(2*DD/64, MM/64), 256>>>(en_out, caw + DD*DD,  cab + DD,  qkv + DD, DD, DD, DD, QKVLD);
        attn_scores<0><<<gAttnS, 256>>>(qkv, en_pad, sc);
        softmax512<<<nSoft, 256>>>(sc);
        attn_av<<<gAttnV, 256>>>(sc, qkv, ao);
        gemm_nt<1,0><<<dim3(DD/64, MM/64), 256>>>(ao, caw + 3*DD*DD, cab + 3*DD, pr, DD, DD, DD, DD);
        add_ln<<<MM, 256>>>(h, pr, ln_g + (size_t)(i*3+1)*DD, ln_b + (size_t)(i*3+1)*DD, a);

        // ---- feed forward ----
        gemm_nt<1,1><<<dim3(FFD/64, MM/64), 256>>>(a,  ff_w1 + (size_t)i*FFD*DD, ff_b1 + (size_t)i*FFD, ff, DD,  DD,  DD,  FFD);
        gemm_nt<1,0><<<dim3(DD/64,  MM/64), 256>>>(ff, ff_w2 + (size_t)i*DD*FFD, ff_b2 + (size_t)i*DD,  pr, FFD, FFD, FFD, DD);
        add_ln<<<MM, 256>>>(a, pr, ln_g + (size_t)(i*3+2)*DD, ln_b + (size_t)(i*3+2)*DD, x);
    }

    // ---- final vocab projection ----
    gemm_nt<1,0><<<dim3(VV/64, MM/64), 256>>>(x, out_w, out_b, out, DD, DD, DD, VV);
}